// round 16
// baseline (speedup 1.0000x reference)
#include <cuda_runtime.h>
#include <cuda_fp16.h>

#define D_FEAT 64
#define N_MAX 100000
#define E_MAX 1200000
#define CONV_BLOCKS 1184   // 148 SMs x 8
#define PREP_THREADS 256

__device__ int g_row_ptr[N_MAX + 1];
// fp16 staged x: N_MAX rows x 16 uint2 (= 32 half2 = 64 features). 12.8MB.
__device__ uint2 g_xh2[N_MAX * 16];
// packed per-edge metadata: {col, float bits of val}. 9.6MB.
__device__ int2 g_meta[E_MAX];

__device__ __forceinline__ unsigned pack_h2(float a, float b) {
    __half2 h = __floats2half2_rn(a, b);
    return *reinterpret_cast<unsigned*>(&h);
}

// Fused prep, three independent sections by blockIdx:
//  [0, CONV_BLOCKS)                 : convert x fp32 -> fp16 (grid-stride)
//  [CONV_BLOCKS, CONV+META)         : pack {col, vals} -> g_meta (4 edges/thr)
//  [CONV+META, ...)                 : row_ptr boundary scatter (4 edges/thr)
__global__ void __launch_bounds__(PREP_THREADS)
prep_kernel(const float4* __restrict__ x4, const int* __restrict__ row,
            const int* __restrict__ col, const float* __restrict__ vals,
            int n4, int n, int E, int meta_blocks) {
    if (blockIdx.x < CONV_BLOCKS) {
        int stride = CONV_BLOCKS * PREP_THREADS;
        for (int i = blockIdx.x * PREP_THREADS + threadIdx.x; i < n4; i += stride) {
            float4 v = __ldg(&x4[i]);
            uint2 p;
            p.x = pack_h2(v.x, v.y);
            p.y = pack_h2(v.z, v.w);
            g_xh2[i] = p;
        }
    } else if (blockIdx.x < CONV_BLOCKS + meta_blocks) {
        // pack meta: 4 edges per thread via int4/float4 loads
        int t = (blockIdx.x - CONV_BLOCKS) * PREP_THREADS + threadIdx.x;
        int i = 4 * t;
        if (i >= E) return;
        if (i + 4 <= E) {
            int4   c = __ldg(reinterpret_cast<const int4*>(col + i));
            float4 v = __ldg(reinterpret_cast<const float4*>(vals + i));
            g_meta[i + 0] = make_int2(c.x, __float_as_int(v.x));
            g_meta[i + 1] = make_int2(c.y, __float_as_int(v.y));
            g_meta[i + 2] = make_int2(c.z, __float_as_int(v.z));
            g_meta[i + 3] = make_int2(c.w, __float_as_int(v.w));
        } else {
            for (int k = i; k < E; k++)
                g_meta[k] = make_int2(__ldg(&col[k]), __float_as_int(__ldg(&vals[k])));
        }
    } else {
        // builder: boundary scatter, 4 edges/thread
        int t = (blockIdx.x - CONV_BLOCKS - meta_blocks) * PREP_THREADS + threadIdx.x;
        int i = 4 * t;
        if (i >= E) return;

        int r0, r1, r2, r3;
        if (i + 3 < E) {
            int4 r4 = __ldg(reinterpret_cast<const int4*>(row + i));
            r0 = r4.x; r1 = r4.y; r2 = r4.z; r3 = r4.w;
        } else {
            r0 = __ldg(&row[i]);
            r1 = (i + 1 < E) ? __ldg(&row[i + 1]) : r0;
            r2 = (i + 2 < E) ? __ldg(&row[i + 2]) : r1;
            r3 = (i + 3 < E) ? __ldg(&row[i + 3]) : r2;
        }
        int prev = (i == 0) ? -1 : __ldg(&row[i - 1]);

        int rr[4] = {r0, r1, r2, r3};
#pragma unroll
        for (int k = 0; k < 4; k++) {
            if (i + k < E) {
                for (int r = prev + 1; r <= rr[k]; r++) g_row_ptr[r] = i + k;
                prev = rr[k];
            }
        }
        if (i + 4 >= E) {
            for (int r = prev + 1; r <= n; r++) g_row_ptr[r] = E;
        }
    }
}

// SpMM: one warp per row, lane owns features {2l,2l+1} as ONE half2.
// Metadata for 2 edges per LDG.128 broadcast (packed int2 pairs); 8-edge
// main batch = 4 meta loads + 8 one-line gathers. fp32 accumulation.
__global__ void __launch_bounds__(128)
spmm_mean_warp_per_row(float* __restrict__ out, int n) {
    int warp_id = (blockIdx.x * blockDim.x + threadIdx.x) >> 5;
    int lane = threadIdx.x & 31;
    if (warp_id >= n) return;

    int s = g_row_ptr[warp_id];
    int e = g_row_ptr[warp_id + 1];

    const __half2* xh = reinterpret_cast<const __half2*>(g_xh2) + lane;
    const int2* mp = g_meta;
    float2 a0 = make_float2(0.f, 0.f);
    float2 a1 = make_float2(0.f, 0.f);

    int i = s;

    // Prologue: align i to even for 16B meta loads (<=1 edge).
    if ((i & 1) && i < e) {
        int2 m = __ldg(&mp[i]);
        float v = __int_as_float(m.y);
        float2 xv = __half22float2(__ldg(&xh[(size_t)m.x * 32]));
        a0.x = fmaf(v, xv.x, a0.x);
        a0.y = fmaf(v, xv.y, a0.y);
        i++;
    }

    // Main: 8 edges = 4 x LDG.128 meta + 8 x 1-line gathers in flight.
    for (; i + 8 <= e; i += 8) {
        int4 m01 = __ldg(reinterpret_cast<const int4*>(mp + i + 0));
        int4 m23 = __ldg(reinterpret_cast<const int4*>(mp + i + 2));
        int4 m45 = __ldg(reinterpret_cast<const int4*>(mp + i + 4));
        int4 m67 = __ldg(reinterpret_cast<const int4*>(mp + i + 6));
        __half2 h0 = __ldg(&xh[(size_t)m01.x * 32]);
        __half2 h1 = __ldg(&xh[(size_t)m01.z * 32]);
        __half2 h2 = __ldg(&xh[(size_t)m23.x * 32]);
        __half2 h3 = __ldg(&xh[(size_t)m23.z * 32]);
        __half2 h4 = __ldg(&xh[(size_t)m45.x * 32]);
        __half2 h5 = __ldg(&xh[(size_t)m45.z * 32]);
        __half2 h6 = __ldg(&xh[(size_t)m67.x * 32]);
        __half2 h7 = __ldg(&xh[(size_t)m67.z * 32]);
        float2 x0 = __half22float2(h0);
        float2 x1 = __half22float2(h1);
        float2 x2 = __half22float2(h2);
        float2 x3 = __half22float2(h3);
        float2 x4 = __half22float2(h4);
        float2 x5 = __half22float2(h5);
        float2 x6 = __half22float2(h6);
        float2 x7 = __half22float2(h7);
        float v0 = __int_as_float(m01.y);
        float v1 = __int_as_float(m01.w);
        float v2 = __int_as_float(m23.y);
        float v3 = __int_as_float(m23.w);
        float v4 = __int_as_float(m45.y);
        float v5 = __int_as_float(m45.w);
        float v6 = __int_as_float(m67.y);
        float v7 = __int_as_float(m67.w);
        a0.x = fmaf(v0, x0.x, a0.x); a0.y = fmaf(v0, x0.y, a0.y);
        a1.x = fmaf(v1, x1.x, a1.x); a1.y = fmaf(v1, x1.y, a1.y);
        a0.x = fmaf(v2, x2.x, a0.x); a0.y = fmaf(v2, x2.y, a0.y);
        a1.x = fmaf(v3, x3.x, a1.x); a1.y = fmaf(v3, x3.y, a1.y);
        a0.x = fmaf(v4, x4.x, a0.x); a0.y = fmaf(v4, x4.y, a0.y);
        a1.x = fmaf(v5, x5.x, a1.x); a1.y = fmaf(v5, x5.y, a1.y);
        a0.x = fmaf(v6, x6.x, a0.x); a0.y = fmaf(v6, x6.y, a0.y);
        a1.x = fmaf(v7, x7.x, a1.x); a1.y = fmaf(v7, x7.y, a1.y);
    }

    // 2-edge step: one LDG.128 each.
    for (; i + 2 <= e; i += 2) {
        int4 m = __ldg(reinterpret_cast<const int4*>(mp + i));
        __half2 h0 = __ldg(&xh[(size_t)m.x * 32]);
        __half2 h1 = __ldg(&xh[(size_t)m.z * 32]);
        float v0 = __int_as_float(m.y);
        float v1 = __int_as_float(m.w);
        float2 x0 = __half22float2(h0);
        float2 x1 = __half22float2(h1);
        a0.x = fmaf(v0, x0.x, a0.x); a0.y = fmaf(v0, x0.y, a0.y);
        a1.x = fmaf(v1, x1.x, a1.x); a1.y = fmaf(v1, x1.y, a1.y);
    }

    // <=1 scalar edge.
    if (i < e) {
        int2 m = __ldg(&mp[i]);
        float v = __int_as_float(m.y);
        float2 xv = __half22float2(__ldg(&xh[(size_t)m.x * 32]));
        a0.x = fmaf(v, xv.x, a0.x);
        a0.y = fmaf(v, xv.y, a0.y);
    }

    int deg = e - s;
    float inv = 1.0f / (float)(deg > 0 ? deg : 1);
    float2 o = make_float2((a0.x + a1.x) * inv, (a0.y + a1.y) * inv);

    *reinterpret_cast<float2*>(&out[(size_t)warp_id * D_FEAT + 2 * lane]) = o;
}

extern "C" void kernel_launch(void* const* d_in, const int* in_sizes, int n_in,
                              void* d_out, int out_size) {
    const float* x    = (const float*)d_in[0];
    const float* vals = (const float*)d_in[1];
    const int*   row  = (const int*)d_in[2];
    const int*   col  = (const int*)d_in[3];
    float* out = (float*)d_out;

    int n = in_sizes[0] / D_FEAT;   // 100000
    int E = in_sizes[1];            // 1200000

    {
        int n4 = n * D_FEAT / 4;
        int quads = (E + 3) / 4;
        int meta_blocks    = (quads + PREP_THREADS - 1) / PREP_THREADS;
        int builder_blocks = (quads + PREP_THREADS - 1) / PREP_THREADS;
        prep_kernel<<<CONV_BLOCKS + meta_blocks + builder_blocks, PREP_THREADS>>>(
            (const float4*)x, row, col, vals, n4, n, E, meta_blocks);
    }
    {
        int threads = 128;
        int rows_per_block = threads / 32;
        int blocks = (n + rows_per_block - 1) / rows_per_block;
        spmm_mean_warp_per_row<<<blocks, threads>>>(out, n);
    }
}

// round 17
// speedup vs baseline: 1.0380x; 1.0380x over previous
#include <cuda_runtime.h>
#include <cuda_fp16.h>

#define D_FEAT 64
#define N_MAX 100000
#define CONV_BLOCKS 1184   // 148 SMs x 8
#define PREP_THREADS 256
#define SPMM_CTAS 2368     // 148 SMs x 16 blocks (one wave at regs<=32)
#define SPMM_THREADS 128

__device__ int g_row_ptr[N_MAX + 1];
// fp16 staged x: N_MAX rows x 16 uint2 (= 32 half2 = 64 features). 12.8MB.
__device__ uint2 g_xh2[N_MAX * 16];

__device__ __forceinline__ unsigned pack_h2(float a, float b) {
    __half2 h = __floats2half2_rn(a, b);
    return *reinterpret_cast<unsigned*>(&h);
}

// Fused prep: blocks [0, CONV_BLOCKS) convert x fp32->fp16 (grid-stride);
// remaining blocks build row_ptr via boundary scatter (4 edges/thread).
__global__ void __launch_bounds__(PREP_THREADS)
prep_kernel(const float4* __restrict__ x4, const int* __restrict__ row,
            int n4, int n, int E) {
    if (blockIdx.x < CONV_BLOCKS) {
        int stride = CONV_BLOCKS * PREP_THREADS;
        for (int i = blockIdx.x * PREP_THREADS + threadIdx.x; i < n4; i += stride) {
            float4 v = __ldg(&x4[i]);
            uint2 p;
            p.x = pack_h2(v.x, v.y);
            p.y = pack_h2(v.z, v.w);
            g_xh2[i] = p;
        }
    } else {
        int t = (blockIdx.x - CONV_BLOCKS) * PREP_THREADS + threadIdx.x;
        int i = 4 * t;
        if (i >= E) return;

        int r0, r1, r2, r3;
        if (i + 3 < E) {
            int4 r4 = __ldg(reinterpret_cast<const int4*>(row + i));
            r0 = r4.x; r1 = r4.y; r2 = r4.z; r3 = r4.w;
        } else {
            r0 = __ldg(&row[i]);
            r1 = (i + 1 < E) ? __ldg(&row[i + 1]) : r0;
            r2 = (i + 2 < E) ? __ldg(&row[i + 2]) : r1;
            r3 = (i + 3 < E) ? __ldg(&row[i + 3]) : r2;
        }
        int prev = (i == 0) ? -1 : __ldg(&row[i - 1]);

        int rr[4] = {r0, r1, r2, r3};
#pragma unroll
        for (int k = 0; k < 4; k++) {
            if (i + k < E) {
                for (int r = prev + 1; r <= rr[k]; r++) g_row_ptr[r] = i + k;
                prev = rr[k];
            }
        }
        if (i + 4 >= E) {
            for (int r = prev + 1; r <= n; r++) g_row_ptr[r] = E;
        }
    }
}

// Persistent SpMM: fixed grid; warp w handles rows w, w+W, w+2W, ...
// No CTA retire boundary between rows; next row's row_ptr pair prefetched
// before the current row's gather loop. Lane owns features {2l,2l+1} (half2),
// 1 cache line per edge gather, fp32 accumulation.
__global__ void __launch_bounds__(SPMM_THREADS, 16)
spmm_mean_persistent(const float* __restrict__ vals,
                     const int* __restrict__ col,
                     float* __restrict__ out,
                     int n) {
    const int W = SPMM_CTAS * (SPMM_THREADS / 32);   // total warps
    int warp0 = (blockIdx.x * SPMM_THREADS + threadIdx.x) >> 5;
    int lane = threadIdx.x & 31;

    const __half2* xh = reinterpret_cast<const __half2*>(g_xh2) + lane;

    int r = warp0;
    if (r >= n) return;

    int s = __ldg(&g_row_ptr[r]);
    int e = __ldg(&g_row_ptr[r + 1]);

    while (true) {
        // Prefetch next row's extent early (overlaps with this row's gathers).
        int rn = r + W;
        int sn = 0, en = 0;
        if (rn < n) {
            sn = __ldg(&g_row_ptr[rn]);
            en = __ldg(&g_row_ptr[rn + 1]);
        }

        float2 a0 = make_float2(0.f, 0.f);
        float2 a1 = make_float2(0.f, 0.f);
        int i = s;

        // Main: 8 edges, 8 one-line gathers in flight.
        for (; i + 8 <= e; i += 8) {
            int c0 = __ldg(&col[i + 0]);
            int c1 = __ldg(&col[i + 1]);
            int c2 = __ldg(&col[i + 2]);
            int c3 = __ldg(&col[i + 3]);
            int c4 = __ldg(&col[i + 4]);
            int c5 = __ldg(&col[i + 5]);
            int c6 = __ldg(&col[i + 6]);
            int c7 = __ldg(&col[i + 7]);
            __half2 h0 = __ldg(&xh[(size_t)c0 * 32]);
            __half2 h1 = __ldg(&xh[(size_t)c1 * 32]);
            __half2 h2 = __ldg(&xh[(size_t)c2 * 32]);
            __half2 h3 = __ldg(&xh[(size_t)c3 * 32]);
            __half2 h4 = __ldg(&xh[(size_t)c4 * 32]);
            __half2 h5 = __ldg(&xh[(size_t)c5 * 32]);
            __half2 h6 = __ldg(&xh[(size_t)c6 * 32]);
            __half2 h7 = __ldg(&xh[(size_t)c7 * 32]);
            float v0 = __ldg(&vals[i + 0]);
            float v1 = __ldg(&vals[i + 1]);
            float v2 = __ldg(&vals[i + 2]);
            float v3 = __ldg(&vals[i + 3]);
            float v4 = __ldg(&vals[i + 4]);
            float v5 = __ldg(&vals[i + 5]);
            float v6 = __ldg(&vals[i + 6]);
            float v7 = __ldg(&vals[i + 7]);
            float2 x0 = __half22float2(h0);
            float2 x1 = __half22float2(h1);
            float2 x2 = __half22float2(h2);
            float2 x3 = __half22float2(h3);
            float2 x4 = __half22float2(h4);
            float2 x5 = __half22float2(h5);
            float2 x6 = __half22float2(h6);
            float2 x7 = __half22float2(h7);
            a0.x = fmaf(v0, x0.x, a0.x); a0.y = fmaf(v0, x0.y, a0.y);
            a1.x = fmaf(v1, x1.x, a1.x); a1.y = fmaf(v1, x1.y, a1.y);
            a0.x = fmaf(v2, x2.x, a0.x); a0.y = fmaf(v2, x2.y, a0.y);
            a1.x = fmaf(v3, x3.x, a1.x); a1.y = fmaf(v3, x3.y, a1.y);
            a0.x = fmaf(v4, x4.x, a0.x); a0.y = fmaf(v4, x4.y, a0.y);
            a1.x = fmaf(v5, x5.x, a1.x); a1.y = fmaf(v5, x5.y, a1.y);
            a0.x = fmaf(v6, x6.x, a0.x); a0.y = fmaf(v6, x6.y, a0.y);
            a1.x = fmaf(v7, x7.x, a1.x); a1.y = fmaf(v7, x7.y, a1.y);
        }

        // 4-edge step.
        for (; i + 4 <= e; i += 4) {
            int c0 = __ldg(&col[i + 0]);
            int c1 = __ldg(&col[i + 1]);
            int c2 = __ldg(&col[i + 2]);
            int c3 = __ldg(&col[i + 3]);
            __half2 h0 = __ldg(&xh[(size_t)c0 * 32]);
            __half2 h1 = __ldg(&xh[(size_t)c1 * 32]);
            __half2 h2 = __ldg(&xh[(size_t)c2 * 32]);
            __half2 h3 = __ldg(&xh[(size_t)c3 * 32]);
            float v0 = __ldg(&vals[i + 0]);
            float v1 = __ldg(&vals[i + 1]);
            float v2 = __ldg(&vals[i + 2]);
            float v3 = __ldg(&vals[i + 3]);
            float2 x0 = __half22float2(h0);
            float2 x1 = __half22float2(h1);
            float2 x2 = __half22float2(h2);
            float2 x3 = __half22float2(h3);
            a0.x = fmaf(v0, x0.x, a0.x); a0.y = fmaf(v0, x0.y, a0.y);
            a1.x = fmaf(v1, x1.x, a1.x); a1.y = fmaf(v1, x1.y, a1.y);
            a0.x = fmaf(v2, x2.x, a0.x); a0.y = fmaf(v2, x2.y, a0.y);
            a1.x = fmaf(v3, x3.x, a1.x); a1.y = fmaf(v3, x3.y, a1.y);
        }

        // Tail: <=3 scalar edges.
        for (; i < e; i++) {
            int   c = __ldg(&col[i]);
            float v = __ldg(&vals[i]);
            float2 xv = __half22float2(__ldg(&xh[(size_t)c * 32]));
            a0.x = fmaf(v, xv.x, a0.x);
            a0.y = fmaf(v, xv.y, a0.y);
        }

        int deg = e - s;
        float inv = 1.0f / (float)(deg > 0 ? deg : 1);
        float2 o = make_float2((a0.x + a1.x) * inv, (a0.y + a1.y) * inv);
        *reinterpret_cast<float2*>(&out[(size_t)r * D_FEAT + 2 * lane]) = o;

        if (rn >= n) break;
        r = rn; s = sn; e = en;
    }
}

extern "C" void kernel_launch(void* const* d_in, const int* in_sizes, int n_in,
                              void* d_out, int out_size) {
    const float* x    = (const float*)d_in[0];
    const float* vals = (const float*)d_in[1];
    const int*   row  = (const int*)d_in[2];
    const int*   col  = (const int*)d_in[3];
    float* out = (float*)d_out;

    int n = in_sizes[0] / D_FEAT;   // 100000
    int E = in_sizes[1];            // 1200000

    {
        int n4 = n * D_FEAT / 4;
        int builder_threads = (E + 3) / 4;
        int builder_blocks = (builder_threads + PREP_THREADS - 1) / PREP_THREADS;
        prep_kernel<<<CONV_BLOCKS + builder_blocks, PREP_THREADS>>>(
            (const float4*)x, row, n4, n, E);
    }
    {
        spmm_mean_persistent<<<SPMM_CTAS, SPMM_THREADS>>>(vals, col, out, n);
    }
}